// round 17
// baseline (speedup 1.0000x reference)
#include <cuda_runtime.h>
#include <cstdint>

// Problem constants (fixed by the reference).
#define N_KEYS   65536
#define EMB      1024
#define KSEL     512
#define BATCH    128
#define NBINS    65536   // top 16 bits of ordered float (256 KB hist).
                         // 64K bins: ~1 hit/bin -> no atomic serialization in
                         // sim (proven 42.2us @ 81.6% DRAM).
#define CAND_CAP 2048    // candidate capacity (expected ~540 used)
#define SEL_BLOCKS 16    // selection blocks inside the fused add kernel
#define ZERO_BLOCKS 64   // blocks 16..79 re-zero the hist post-selection

// -------- scratch (no allocations allowed: __device__ globals) --------
// Zero-initialized at module load. Re-arm protocol per invocation:
//   g_ready              : reset to 0 by sim_kernel block 0 (stream-ordered
//                          after the previous fused kernel completed).
//   g_hist               : zeroed by fused blocks 16..79 AFTER g_ready
//                          (cannot race selection's hist reads).
//   g_ccnt/g_done2/g_bar : reset by the elected selection block post-flag.
__device__ float              g_sims[N_KEYS];
__device__ unsigned int       g_hist[NBINS];
__device__ int                g_chunk[256];     // 256-bin chunk sums
__device__ unsigned long long g_cand[CAND_CAP];
__device__ unsigned int       g_ccnt;
__device__ int                g_topk[KSEL];
__device__ unsigned int       g_done2, g_bar;
__device__ volatile unsigned int g_ready;

// Monotone float -> uint transform: a > b  <=>  ford(a) > ford(b)
__device__ __forceinline__ unsigned int ford(float f) {
    unsigned int u = __float_as_uint(f);
    return (u & 0x80000000u) ? ~u : (u | 0x80000000u);
}

// ---------------------------------------------------------------------
// K1: PURE sims + histogram (DRAM-bound). No tail, no election, no fence.
// One warp per key row, 8 warps/block, grid = 8192.  (42.2us @ 81.6%)
// ---------------------------------------------------------------------
__global__ void __launch_bounds__(256)
sim_kernel(const float* __restrict__ keys,
           const float* __restrict__ query) {
    if (blockIdx.x == 0 && threadIdx.x == 0) g_ready = 0u;

    const int warp = threadIdx.x >> 5;
    const int lane = threadIdx.x & 31;
    const int n    = blockIdx.x * 8 + warp;

    const float4* k4 = reinterpret_cast<const float4*>(keys) + (size_t)n * (EMB / 4);
    const float4* q4 = reinterpret_cast<const float4*>(query);

    float dot = 0.f, sq = 0.f;
#pragma unroll
    for (int l = 0; l < 8; ++l) {
        float4 kv = k4[lane + 32 * l];
        float4 qv = __ldg(&q4[lane + 32 * l]);
        dot = fmaf(kv.x, qv.x, dot);
        dot = fmaf(kv.y, qv.y, dot);
        dot = fmaf(kv.z, qv.z, dot);
        dot = fmaf(kv.w, qv.w, dot);
        sq  = fmaf(kv.x, kv.x, sq);
        sq  = fmaf(kv.y, kv.y, sq);
        sq  = fmaf(kv.z, kv.z, sq);
        sq  = fmaf(kv.w, kv.w, sq);
    }
#pragma unroll
    for (int o = 16; o > 0; o >>= 1) {
        dot += __shfl_xor_sync(0xFFFFFFFFu, dot, o);
        sq  += __shfl_xor_sync(0xFFFFFFFFu, sq,  o);
    }
    if (lane == 0) {
        float nrm = __fsqrt_rn(fmaxf(sq, 1e-16f));   // max(norm, 1e-8)
        float sim = __fdiv_rn(dot, nrm);             // q-norm scale omitted (order-invariant)
        g_sims[n] = sim;
        atomicAdd(&g_hist[ford(sim) >> 16], 1u);     // 64K bins: ~1 hit/bin
    }
}

// ---------------------------------------------------------------------
// K2 (fused): out[b,k,:] = x[b,k,:] + prompts[topk[k], :], with the
// ENTIRE top-k selection done by blocks 0..15 inside this kernel.
//  - Every block issues its x-row load FIRST (overlaps selection).
//  - Blocks 0..15 (dispatch-order first => wave-1 co-resident => both
//    spin loops progress): reduce own 16 KB hist slice -> g_chunk; mini
//    grid barrier; redundant 2-level smem scan -> threshold T; compact
//    own g_sims slice; elected last block ranks ~540 candidates exactly
//    (key=(ord<<32)|~idx == jax top_k desc-val/asc-idx order), publishes
//    g_topk, sets g_ready, resets counters.
//  - Blocks 16..79: after g_ready, each zeroes 4 KB of hist (distributed;
//    R10 evidence: single-block 256 KB zero costs 13-27us).
//  - All blocks: t0 polls g_ready with short nanosleep, then gather+add.
// ---------------------------------------------------------------------
__global__ void __launch_bounds__(256)
add_fused_kernel(const float4* __restrict__ x,
                 const float4* __restrict__ prompts,
                 float4* __restrict__ out) {
    const int bid = blockIdx.x;            // b*512 + k
    const int k   = bid & (KSEL - 1);
    const int t   = threadIdx.x;           // 0..255

    // Issue the x-row load immediately: it flows while selection runs.
    const size_t xo = (size_t)bid * (EMB / 4) + t;
    float4 xv = __ldcs(&x[xo]);                          // streaming read-once

    __shared__ int s_sc[256];
    __shared__ int s_bins[256];
    __shared__ int s_cstar, s_bstar;
    __shared__ unsigned int s_last;
    __shared__ unsigned long long s_key[CAND_CAP];       // 16 KB

    if (bid < SEL_BLOCKS) {
        const int lane = t & 31;

        // ---- Phase A1: reduce own 4096-bin slice to 16 chunk sums ----
        {
            const uint4* h4 = reinterpret_cast<const uint4*>(g_hist);
            int s = 0;
#pragma unroll
            for (int i = 0; i < 4; ++i) {                // coalesced: stride-256 uint4
                uint4 v = h4[bid * 1024 + i * 256 + t];
                s += (int)(v.x + v.y + v.z + v.w);
            }
            // s now holds 16 bins from 4 separated places? NO — keep the
            // layout simple & provably correct: redo with contiguous-per-
            // thread mapping via shared accumulation instead.
            s_sc[t] = s;                                 // partial: 16 bins, mixed
        }
        __syncthreads();
        // s_sc[t] holds sum of bins {bid*16384 + (i*256+t)*4 .. +3} over i.
        // Chunk c (256 bins) = uint4s [c*64 .. c*64+63] of this slice:
        // thread t contributed uint4s {t, 256+t, 512+t, 768+t}; uint4 j
        // belongs to chunk j>>6. So chunk sums = segmented reduction of
        // s_sc by (uint4 index >> 6). Rebuild cleanly: thread groups of 64
        // threads t in [c*64,(c+1)*64) cover uint4s {c*64+i*256+tt}? Not
        // aligned. Use a direct smem tree instead: each thread's 4 uint4s
        // span 4 DIFFERENT chunks (j = t + 256i -> chunk (t>>6) + 4i).
        // So per-thread partial s is NOT a single-chunk quantity. Redo:
        // accumulate per-chunk in smem with atomics-free two-step.
        {
            // Each thread re-reads its 4 uint4s and adds each to its own
            // chunk's accumulator via smem atomicAdd (64 adds per chunk,
            // 16 chunks — negligible contention, all in smem).
            if (t < 16) s_bins[t] = 0;                   // reuse s_bins[0..15]
            __syncthreads();
            const uint4* h4 = reinterpret_cast<const uint4*>(g_hist);
#pragma unroll
            for (int i = 0; i < 4; ++i) {
                const int j = i * 256 + t;               // uint4 index in slice
                uint4 v = h4[bid * 1024 + j];
                atomicAdd((int*)&s_bins[j >> 6],
                          (int)(v.x + v.y + v.z + v.w)); // chunk = 64 uint4s
            }
            __syncthreads();
            if (t < 16) g_chunk[16 * bid + t] = s_bins[t];
        }

        // ---- mini grid barrier among the 16 selection blocks ----
        __syncthreads();
        if (t == 0) {
            __threadfence();                             // release g_chunk
            atomicAdd(&g_bar, 1u);
            while (*((volatile unsigned int*)&g_bar) < SEL_BLOCKS) { }
        }
        __syncthreads();
        __threadfence();                                 // acquire

        // ---- Phase A2: threshold (redundant per block, all smem) ----
        s_sc[t] = g_chunk[t];
        __syncthreads();
        for (int d = 1; d < 256; d <<= 1) {              // suffix scan 256 chunks
            int v = s_sc[t] + ((t + d < 256) ? s_sc[t + d] : 0);
            __syncthreads();
            s_sc[t] = v;
            __syncthreads();
        }
        if (s_sc[t] >= KSEL && (t == 255 || s_sc[t + 1] < KSEL)) s_cstar = t;
        __syncthreads();
        const int cstar = s_cstar;
        const int above = (cstar < 255) ? s_sc[cstar + 1] : 0;

        s_bins[t] = (int)g_hist[cstar * 256 + t];        // winning chunk's bins
        __syncthreads();
        for (int d = 1; d < 256; d <<= 1) {
            int v = s_bins[t] + ((t + d < 256) ? s_bins[t + d] : 0);
            __syncthreads();
            s_bins[t] = v;
            __syncthreads();
        }
        if (above + s_bins[t] >= KSEL &&
            (t == 255 || above + s_bins[t + 1] < KSEL)) s_bstar = t;
        __syncthreads();
        const unsigned int T = ((unsigned int)(cstar * 256 + s_bstar)) << 16;

        // ---- Phase B: compact own g_sims slice (coalesced, 4x) ----
#pragma unroll
        for (int i = 0; i < 4; ++i) {
            const int i4 = bid * 1024 + i * 256 + t;
            float4 v = reinterpret_cast<const float4*>(g_sims)[i4];
            unsigned int u0 = ford(v.x), u1 = ford(v.y), u2 = ford(v.z), u3 = ford(v.w);
            int base = i4 * 4;
            if (u0 >= T) { unsigned int p = atomicAdd(&g_ccnt, 1u); if (p < CAND_CAP)
                g_cand[p] = ((unsigned long long)u0 << 32) | (unsigned int)~(unsigned int)(base + 0); }
            if (u1 >= T) { unsigned int p = atomicAdd(&g_ccnt, 1u); if (p < CAND_CAP)
                g_cand[p] = ((unsigned long long)u1 << 32) | (unsigned int)~(unsigned int)(base + 1); }
            if (u2 >= T) { unsigned int p = atomicAdd(&g_ccnt, 1u); if (p < CAND_CAP)
                g_cand[p] = ((unsigned long long)u2 << 32) | (unsigned int)~(unsigned int)(base + 2); }
            if (u3 >= T) { unsigned int p = atomicAdd(&g_ccnt, 1u); if (p < CAND_CAP)
                g_cand[p] = ((unsigned long long)u3 << 32) | (unsigned int)~(unsigned int)(base + 3); }
        }

        // ---- election among the 16 selection blocks ----
        __syncthreads();
        if (t == 0) {
            __threadfence();
            s_last = (atomicAdd(&g_done2, 1u) == SEL_BLOCKS - 1) ? 1u : 0u;
        }
        __syncthreads();

        if (s_last) {
            __threadfence();                             // acquire all candidates

            // ---- Phase C: exact ranking of ~540 candidates ----
            const unsigned int ccnt = g_ccnt;
            const int cnt = (ccnt < CAND_CAP) ? (int)ccnt : CAND_CAP;
            for (int i = t; i < cnt; i += 256) s_key[i] = g_cand[i];
            __syncthreads();
            for (int i = t; i < cnt; i += 256) {
                const unsigned long long ki = s_key[i];
                int rank = 0;
                for (int j = 0; j < cnt; ++j)            // broadcast smem reads
                    rank += (s_key[j] > ki);
                if (rank < KSEL)
                    g_topk[rank] = (int)(~(unsigned int)(ki & 0xFFFFFFFFull));
            }
            __syncthreads();
            if (t == 0) {
                g_ccnt = 0u; g_done2 = 0u; g_bar = 0u;   // re-arm counters
                __threadfence();
                g_ready = 1u;                            // publish
            }
        }
    }

    // ---- all blocks: wait until g_topk is published ----
    if (t == 0) {
        while (g_ready == 0u) __nanosleep(64);
    }
    __syncthreads();
    __threadfence();                                     // acquire g_topk

    // Blocks 16..79: distributed hist re-zero (post-selection, 4 KB each).
    if (bid >= SEL_BLOCKS && bid < SEL_BLOCKS + ZERO_BLOCKS)
        reinterpret_cast<uint4*>(g_hist)[(bid - SEL_BLOCKS) * 256 + t] =
            make_uint4(0u, 0u, 0u, 0u);

    const int row = g_topk[k];
    float4 pv = __ldg(&prompts[(size_t)row * (EMB / 4) + t]);
    xv.x += pv.x; xv.y += pv.y; xv.z += pv.z; xv.w += pv.w;
    __stcs(&out[xo], xv);                                // streaming write-once
}

// ---------------------------------------------------------------------
extern "C" void kernel_launch(void* const* d_in, const int* in_sizes, int n_in,
                              void* d_out, int out_size) {
    const float* x       = (const float*)d_in[0];   // [128, 512, 1024]
    const float* query   = (const float*)d_in[1];   // [1024]
    const float* keys    = (const float*)d_in[2];   // [65536, 1024]
    const float* prompts = (const float*)d_in[3];   // [65536, 1024]
    float* out           = (float*)d_out;           // [128, 512, 1024]

    sim_kernel<<<N_KEYS / 8, 256>>>(keys, query);
    add_fused_kernel<<<BATCH * KSEL, 256>>>(reinterpret_cast<const float4*>(x),
                                            reinterpret_cast<const float4*>(prompts),
                                            reinterpret_cast<float4*>(out));
}